// round 12
// baseline (speedup 1.0000x reference)
#include <cuda_runtime.h>

#define B        1024
#define NUM_VARS 2048
#define LEAVES   4096
#define LEVELS   12
#define WIDTH    4096
#define NINT     (LEVELS * WIDTH)          // 49152
#define TOTAL    (LEAVES + NINT)           // 53248

#define NTHR     512
#define BBK      8                  // batch columns per block
#define NBLK     (B / BBK)          // 128 blocks
#define NDISC    384                // discovery threads (warps 0-11)

#define PCAP     1536               // max plan nodes on the fast path
#define LCAP2    256                // per-level slot capacity (fixed stride)
#define HSZ      4096               // hash slots (power of two)
#define VPAD     9                  // val stride (9 coprime 32 -> conflict-free)
#define XPAD     2052               // floats; 8208 B row stride (16B aligned)

// Dense-fallback value buffer (touched only if plan exceeds caps).
__device__ float g_dense[(size_t)NINT * B];

// ---- smem layout (bytes) ----
#define SM_PCH   0                               // int4[PCAP]   raw children  24576
#define SM_SCH   (SM_PCH + PCAP * 16)            // int2[12*256] sorted plan   24576
#define SM_XROW  (SM_SCH + LEVELS * LCAP2 * 8)   // float[8*XPAD]              65664
#define SM_VAL   (SM_XROW + BBK * XPAD * 4)      // float[PCAP*VPAD]           55296
#define SM_HKEY  (SM_VAL + PCAP * VPAD * 4)      // int[HSZ]                   16384
#define SM_PORIG (SM_HKEY + HSZ * 4)             // int[PCAP]                   6144
#define SM_META  (SM_PORIG + PCAP * 4)           // int[PCAP] level<<16|rank    6144
#define SM_BITS  (SM_META + PCAP * 4)            // uint[NINT/32]               6144
#define SM_HVAL  (SM_BITS + NINT / 8)            // ushort[HSZ]                 8192
#define SM_SDST  (SM_HVAL + HSZ * 2)             // ushort[12*256]              6144
#define SM_POP   (SM_SDST + LEVELS * LCAP2 * 2)  // uchar[PCAP]                 1536
#define SM_TOTAL (SM_POP + PCAP)                 // 220,800 B

#define BAR1() asm volatile("bar.sync 1, %0;" :: "n"(NDISC) : "memory")

// Resolve plan entry j into its fixed level slot. Safe once j's expansion
// wave has passed a barrier (children cids published; hash insert-monotonic).
__device__ __forceinline__ void resolve_entry(
    int j, const int4* pch, const int* meta, const unsigned char* pop,
    const int* hkey, const unsigned short* hval,
    int2* sch, unsigned short* sdst)
{
    const int mt = meta[j];
    const int r2 = mt & 0xFFFF;
    if (r2 >= LCAP2) return;                    // overflow: sFail path owns it
    const int p  = ((mt >> 16) << 8) + r2;      // level*256 + rank
    const int4 ch = pch[j];
    unsigned f[4];
    const int cs[4] = {ch.x, ch.y, ch.z, ch.w};
    #pragma unroll
    for (int q = 0; q < 4; ++q) {
        const int c = cs[q];
        if (c < LEAVES) f[q] = 0x8000u | (unsigned)c;
        else {
            unsigned slot = ((unsigned)c * 2654435761u) & (HSZ - 1);
            while (hkey[slot] != c) slot = (slot + 1) & (HSZ - 1);
            f[q] = hval[slot];
        }
    }
    f[0] |= ((unsigned)pop[j] & 1u) << 14;      // op in bit14 of field0
    sch[p]  = make_int2((int)(f[0] | (f[1] << 16)), (int)(f[2] | (f[3] << 16)));
    sdst[p] = (unsigned short)j;                // dest cid
}

__global__ void __launch_bounds__(NTHR, 1)
eval_all(const float* __restrict__ x,
         const int*   __restrict__ child_idx,
         const int*   __restrict__ op_type,
         float*       __restrict__ out)
{
    extern __shared__ unsigned char sm[];
    int4*           pch   = (int4*)          (sm + SM_PCH);
    int2*           sch   = (int2*)          (sm + SM_SCH);
    float*          xrow  = (float*)         (sm + SM_XROW);
    float*          val   = (float*)         (sm + SM_VAL);
    int*            hkey  = (int*)           (sm + SM_HKEY);
    int*            porig = (int*)           (sm + SM_PORIG);
    int*            meta  = (int*)           (sm + SM_META);
    unsigned int*   bits  = (unsigned int*)  (sm + SM_BITS);
    unsigned short* hval  = (unsigned short*)(sm + SM_HVAL);
    unsigned short* sdst  = (unsigned short*)(sm + SM_SDST);
    unsigned char*  pop   = (unsigned char*) (sm + SM_POP);

    __shared__ int scnt, sE, sF, sFail, sRs;
    __shared__ int slcnt[LEVELS];

    const int tid = threadIdx.x;
    const int blk = blockIdx.x;

    if (tid < NDISC) {
        // ===== warps 0-11: wave BFS discovery + overlapped resolution =====
        for (int i = tid; i < HSZ; i += NDISC) hkey[i] = -1;
        for (int i = tid; i < NINT / 32; i += NDISC) bits[i] = 0u;
        BAR1();
        if (tid == 0) {
            for (int l = 0; l < LEVELS; ++l) slcnt[l] = 0;
            scnt = 1; sFail = 0; sRs = 0;
            porig[0] = TOTAL - 1;                  // root = plan idx (cid) 0
            meta[0]  = (11 << 16) | 0;
            slcnt[11] = 1;
        }
        BAR1();

        int s = 0, e = 1;
        while (s < e) {
            const int fsz = e - s;
            if (tid < fsz || tid >= ((fsz + 31) & ~31)) {
                // ---- expansion over frontier [s, e) ----
                for (int i = s + tid; i < e; i += NDISC) {
                    const int ni = porig[i] - LEAVES;
                    const int4 ch = ((const int4*)child_idx)[ni];
                    pch[i] = ch;
                    pop[i] = (unsigned char)op_type[ni];
                    const int cs[4] = {ch.x, ch.y, ch.z, ch.w};
                    #pragma unroll
                    for (int f = 0; f < 4; ++f) {
                        const int c = cs[f];
                        if (c < LEAVES) continue;
                        const int ci = c - LEAVES;
                        const unsigned m = 1u << (ci & 31);
                        const unsigned old = atomicOr(&bits[ci >> 5], m);
                        if (!(old & m)) {                     // we claimed c
                            const int cid = atomicAdd(&scnt, 1);
                            if (cid >= PCAP) { sFail = 1; continue; }
                            porig[cid] = c;
                            const int l2 = ci >> 12;          // / WIDTH
                            const int r2 = atomicAdd(&slcnt[l2], 1);
                            if (r2 >= LCAP2) sFail = 1;
                            meta[cid] = (l2 << 16) | r2;
                            // write-only hash insert (lookups post-barrier)
                            unsigned slot = ((unsigned)c * 2654435761u) & (HSZ - 1);
                            while (atomicCAS(&hkey[slot], -1, c) != -1)
                                slot = (slot + 1) & (HSZ - 1);
                            hval[slot] = (unsigned short)cid;
                        }
                    }
                }
            }
            // ---- overlapped resolution of earlier waves by idle threads ----
            // (entries [sRs, s) were expanded in prior waves; barrier-ordered)
            if (tid >= fsz) {
                const int idle = NDISC - fsz;          // >= 1 here
                for (int j = sRs + (tid - fsz); j < s; j += idle)
                    resolve_entry(j, pch, meta, pop, hkey, hval, sch, sdst);
            }
            BAR1();                                   // wave's appends/resolves done
            if (tid == 0) {
                sE = (scnt < PCAP) ? scnt : PCAP;
                sF = sFail;
                if (fsz < NDISC) sRs = s;             // [0,s) now resolved
            }
            BAR1();                                   // snapshot stable
            s = e; e = sE;
            if (sF) break;
        }
    } else {
        // =============== warps 12-15: stage x rows into smem ===============
        for (int idx = tid - NDISC; idx < (BBK * NUM_VARS) / 4; idx += NTHR - NDISC) {
            const int r  = idx >> 9;                  // /512 float4 per row
            const int c4 = idx & 511;
            const float4 v =
                ((const float4*)x)[(size_t)(blk * BBK + r) * (NUM_VARS / 4) + c4];
            *(float4*)&xrow[r * XPAD + c4 * 4] = v;
        }
    }
    __syncthreads();   // JOIN: discovery + staging complete

    const int n = (scnt < PCAP) ? scnt : PCAP;

    if (sF) {
        // =============== dense fallback (worst case only) ===============
        for (int l = 0; l < LEVELS; ++l) {
            for (int k = tid; k < WIDTH * BBK; k += NTHR) {
                const int w2 = k >> 3, b2 = k & 7, bg2 = blk * BBK + b2;
                const int ni = l * WIDTH + w2;
                const int4 ch = ((const int4*)child_idx)[ni];
                const int cs[4] = {ch.x, ch.y, ch.z, ch.w};
                float v[4];
                #pragma unroll
                for (int f = 0; f < 4; ++f) {
                    const int c = cs[f];
                    if (c < LEAVES) {
                        const float xv = xrow[b2 * XPAD + (c & (NUM_VARS - 1))];
                        v[f] = (c < NUM_VARS) ? xv : 1.0f - xv;
                    } else {
                        v[f] = g_dense[(size_t)(c - LEAVES) * B + bg2];
                    }
                }
                const float r = op_type[ni] ? (v[0] + v[1]) + (v[2] + v[3])
                                            : (v[0] * v[1]) * (v[2] * v[3]);
                g_dense[(size_t)ni * B + bg2] = r;
            }
            __syncthreads();
        }
        if (tid < BBK)
            out[blk * BBK + tid] = g_dense[(size_t)(NINT - 1) * B + blk * BBK + tid];
        return;
    }

    // ---- residual resolution (entries from the final waves), all 512 ----
    for (int j = sRs + tid; j < n; j += NTHR)
        resolve_entry(j, pch, meta, pop, hkey, hval, sch, sdst);
    __syncthreads();                              // plan finalized

    // ====== forward: 64 node-lanes x 8 batch columns, all-SMEM ======
    const int lane = tid >> 3;                    // 0..63
    const int bb   = tid & 7;

    for (int l = 0; l < LEVELS; ++l) {
        const int cnt  = slcnt[l];
        const int base = l << 8;                  // l * LCAP2
        for (int j = lane; j < cnt; j += 64) {
            const int2 e = sch[base + j];
            const unsigned f0 = (unsigned)e.x & 0xFFFFu;
            const unsigned f1 = (unsigned)e.x >> 16;
            const unsigned f2 = (unsigned)e.y & 0xFFFFu;
            const unsigned f3 = (unsigned)e.y >> 16;
            const int op = (f0 >> 14) & 1;
            #define FETCH(ff) (((ff) & 0x8000u)                               \
                ? (((ff) & 2048u)                                             \
                    ? 1.0f - xrow[bb * XPAD + (int)((ff) & 2047u)]            \
                    :        xrow[bb * XPAD + (int)((ff) & 2047u)])           \
                : val[(int)((ff) & 0xFFFu) * VPAD + bb])
            const float v0 = FETCH(f0 & 0x8FFFu);
            const float v1 = FETCH(f1);
            const float v2 = FETCH(f2);
            const float v3 = FETCH(f3);
            #undef FETCH
            const float r = op ? (v0 + v1) + (v2 + v3)
                               : (v0 * v1) * (v2 * v3);
            val[(int)sdst[base + j] * VPAD + bb] = r;
        }
        __syncthreads();
    }

    if (tid < BBK) out[blk * BBK + tid] = val[tid];   // root cid = 0
}

// ---------------------------------------------------------------------------
// Launch: x (f32), child_idx (i32), op_type (i32). One kernel; capturable.
// ---------------------------------------------------------------------------
extern "C" void kernel_launch(void* const* d_in, const int* in_sizes, int n_in,
                              void* d_out, int out_size) {
    const float* x         = (const float*)d_in[0];
    const int*   child_idx = (const int*)  d_in[1];
    const int*   op_type   = (const int*)  d_in[2];
    float*       out       = (float*)d_out;

    cudaFuncSetAttribute(eval_all,
                         cudaFuncAttributeMaxDynamicSharedMemorySize, SM_TOTAL);
    eval_all<<<NBLK, NTHR, SM_TOTAL>>>(x, child_idx, op_type, out);
}

// round 13
// speedup vs baseline: 27.8444x; 27.8444x over previous
#include <cuda_runtime.h>

#define B        1024
#define NUM_VARS 2048
#define LEAVES   4096
#define LEVELS   12
#define WIDTH    4096
#define NINT     (LEVELS * WIDTH)          // 49152
#define TOTAL    (LEAVES + NINT)           // 53248

#define NTHR     512
#define BBK      8                  // batch columns per block (= forward warps)
#define NBLK     (B / BBK)          // 128 blocks
#define NDISC    384                // discovery threads (warps 0-11)

#define PCAP     1536               // max plan nodes on the fast path
#define HSZ      4096               // hash slots (power of two)
#define VPAD     9                  // val stride (9 coprime 32 -> conflict-free)
#define XPAD     2052               // floats; 8208 B row stride (16B aligned)

// Dense-fallback value buffer (touched only if plan exceeds PCAP).
__device__ float g_dense[(size_t)NINT * B];

// ---- smem layout (bytes), 16B alignment where needed ----
#define SM_PCH   0                               // int4[PCAP]   raw children  24576
#define SM_SCH   (SM_PCH + PCAP * 16)            // int2[PCAP]   sorted plan   12288
#define SM_XROW  (SM_SCH + PCAP * 8)             // float[8*XPAD]              65664
#define SM_VAL   (SM_XROW + BBK * XPAD * 4)      // float[PCAP*VPAD]           55296
#define SM_HKEY  (SM_VAL + PCAP * VPAD * 4)      // int[HSZ]                   16384
#define SM_PORIG (SM_HKEY + HSZ * 4)             // int[PCAP]                   6144
#define SM_META  (SM_PORIG + PCAP * 4)           // int[PCAP] level<<16|rank    6144
#define SM_BITS  (SM_META + PCAP * 4)            // uint[NINT/32]               6144
#define SM_HVAL  (SM_BITS + NINT / 8)            // ushort[HSZ]                 8192
#define SM_SCID  (SM_HVAL + HSZ * 2)             // ushort[PCAP]                3072
#define SM_POP   (SM_SCID + PCAP * 2)            // uchar[PCAP]                 1536
#define SM_TOTAL (SM_POP + PCAP)                 // 205,440 B

#define BAR1() asm volatile("bar.sync 1, %0;" :: "n"(NDISC) : "memory")

__global__ void __launch_bounds__(NTHR, 1)
eval_all(const float* __restrict__ x,
         const int*   __restrict__ child_idx,
         const int*   __restrict__ op_type,
         float*       __restrict__ out)
{
    extern __shared__ unsigned char sm[];
    int4*           pch   = (int4*)          (sm + SM_PCH);
    int2*           sch   = (int2*)          (sm + SM_SCH);
    float*          xrow  = (float*)         (sm + SM_XROW);
    float*          val   = (float*)         (sm + SM_VAL);
    int*            hkey  = (int*)           (sm + SM_HKEY);
    int*            porig = (int*)           (sm + SM_PORIG);
    int*            meta  = (int*)           (sm + SM_META);
    unsigned int*   bits  = (unsigned int*)  (sm + SM_BITS);
    unsigned short* hval  = (unsigned short*)(sm + SM_HVAL);
    unsigned short* scid  = (unsigned short*)(sm + SM_SCID);
    unsigned char*  pop   = (unsigned char*) (sm + SM_POP);

    __shared__ int scnt, sFail;
    __shared__ int slcnt[LEVELS], soff[LEVELS + 1];

    const int tid = threadIdx.x;
    const int blk = blockIdx.x;

    if (tid < NDISC) {
        // =============== warps 0-11: worklist-BFS discovery ===============
        {   // vectorized table init
            const int4 m1 = make_int4(-1, -1, -1, -1);
            const int4 z0 = make_int4(0, 0, 0, 0);
            for (int i = tid; i < HSZ / 4; i += NDISC)      ((int4*)hkey)[i] = m1;
            for (int i = tid; i < NINT / 128; i += NDISC)   ((int4*)bits)[i] = z0;
        }
        BAR1();
        if (tid == 0) {
            for (int l = 0; l < LEVELS; ++l) slcnt[l] = 0;
            scnt = 1; sFail = 0;
            porig[0] = TOTAL - 1;                  // root = plan idx (cid) 0
            meta[0]  = (11 << 16) | 0;
            slcnt[11] = 1;
        }
        BAR1();

        int s = 0, e = 1;
        while (s < e) {
            for (int i = s + tid; i < e; i += NDISC) {
                const int ni = porig[i] - LEAVES;
                const int4 ch = ((const int4*)child_idx)[ni];
                pch[i] = ch;
                pop[i] = (unsigned char)op_type[ni];
                const int cs[4] = {ch.x, ch.y, ch.z, ch.w};
                #pragma unroll
                for (int f = 0; f < 4; ++f) {
                    const int c = cs[f];
                    if (c < LEAVES) continue;
                    const int ci = c - LEAVES;
                    const unsigned int m = 1u << (ci & 31);
                    const unsigned int old = atomicOr(&bits[ci >> 5], m);
                    if (!(old & m)) {                         // we claimed c
                        const int cid = atomicAdd(&scnt, 1);
                        if (cid >= PCAP) { sFail = 1; continue; }
                        porig[cid] = c;
                        const int l2 = ci >> 12;              // / WIDTH
                        const int r2 = atomicAdd(&slcnt[l2], 1);
                        meta[cid] = (l2 << 16) | r2;
                        // write-only hash insert (lookups happen post-bar)
                        unsigned slot = ((unsigned)c * 2654435761u) & (HSZ - 1);
                        while (atomicCAS(&hkey[slot], -1, c) != -1)
                            slot = (slot + 1) & (HSZ - 1);
                        hval[slot] = (unsigned short)cid;
                    }
                }
            }
            BAR1();   // all of this wave's appends complete; scnt now stable.
            // Every thread computes the identical snapshot directly — the
            // old tid0-publish + second barrier is redundant.
            s = e;
            const int sc = *(volatile int*)&scnt;
            e = (sc < PCAP) ? sc : PCAP;
            if (*(volatile int*)&sFail) break;
        }
    } else {
        // =============== warps 12-15: stage x rows into smem ===============
        for (int idx = tid - NDISC; idx < (BBK * NUM_VARS) / 4; idx += NTHR - NDISC) {
            const int r  = idx >> 9;                  // /512 float4 per row
            const int c4 = idx & 511;
            const float4 v =
                ((const float4*)x)[(size_t)(blk * BBK + r) * (NUM_VARS / 4) + c4];
            *(float4*)&xrow[r * XPAD + c4 * 4] = v;
        }
    }
    __syncthreads();   // join: discovery + staging complete; scnt/sFail stable

    const int n = (*(volatile int*)&scnt < PCAP) ? scnt : PCAP;

    if (*(volatile int*)&sFail) {
        // =============== dense fallback (worst case only) ===============
        for (int l = 0; l < LEVELS; ++l) {
            for (int k = tid; k < WIDTH * BBK; k += NTHR) {
                const int w2 = k >> 3, b2 = k & 7, bg2 = blk * BBK + b2;
                const int ni = l * WIDTH + w2;
                const int4 ch = ((const int4*)child_idx)[ni];
                const int cs[4] = {ch.x, ch.y, ch.z, ch.w};
                float v[4];
                #pragma unroll
                for (int f = 0; f < 4; ++f) {
                    const int c = cs[f];
                    if (c < LEAVES) {
                        const float xv = xrow[b2 * XPAD + (c & (NUM_VARS - 1))];
                        v[f] = (c < NUM_VARS) ? xv : 1.0f - xv;
                    } else {
                        v[f] = g_dense[(size_t)(c - LEAVES) * B + bg2];
                    }
                }
                const float r = op_type[ni] ? (v[0] + v[1]) + (v[2] + v[3])
                                            : (v[0] * v[1]) * (v[2] * v[3]);
                g_dense[(size_t)ni * B + bg2] = r;
            }
            __syncthreads();
        }
        if (tid < BBK)
            out[blk * BBK + tid] = g_dense[(size_t)(NINT - 1) * B + blk * BBK + tid];
        return;
    }

    // ---- prefix offsets for level-sorted plan ----
    if (tid == 0) {
        int o = 0;
        for (int l = 0; l < LEVELS; ++l) { soff[l] = o; o += slcnt[l]; }
        soff[LEVELS] = o;
    }
    __syncthreads();

    // ---- resolution: encode + scatter entries into level order (all 512) ----
    // 16-bit operand field: bit15 = leaf, bits0-11 = leaf id or cid.
    // op stored in bit14 of field0. Entry's own cid recorded in scid[].
    for (int i = tid; i < n; i += NTHR) {
        const int4 ch = pch[i];
        const int mt = meta[i];
        const int j  = soff[mt >> 16] + (mt & 0xFFFF);
        unsigned f[4];
        const int cs[4] = {ch.x, ch.y, ch.z, ch.w};
        #pragma unroll
        for (int q = 0; q < 4; ++q) {
            const int c = cs[q];
            if (c < LEAVES) f[q] = 0x8000u | (unsigned)c;
            else {
                unsigned slot = ((unsigned)c * 2654435761u) & (HSZ - 1);
                while (hkey[slot] != c) slot = (slot + 1) & (HSZ - 1);
                f[q] = hval[slot];
            }
        }
        f[0] |= ((unsigned)pop[i] & 1u) << 14;
        sch[j]  = make_int2((int)(f[0] | (f[1] << 16)), (int)(f[2] | (f[3] << 16)));
        scid[j] = (unsigned short)i;
    }
    __syncthreads();                              // plan finalized

    // ====== forward: 64 node-lanes x 8 batch columns, all-SMEM ======
    const int lane = tid >> 3;                    // 0..63
    const int bb   = tid & 7;

    for (int l = 0; l < LEVELS; ++l) {
        const int s0 = soff[l], e0 = soff[l + 1];
        for (int j = s0 + lane; j < e0; j += 64) {
            const int2 e = sch[j];
            const unsigned f0 = (unsigned)e.x & 0xFFFFu;
            const unsigned f1 = (unsigned)e.x >> 16;
            const unsigned f2 = (unsigned)e.y & 0xFFFFu;
            const unsigned f3 = (unsigned)e.y >> 16;
            const int op = (f0 >> 14) & 1;
            #define FETCH(ff) (((ff) & 0x8000u)                               \
                ? (((ff) & 2048u)                                             \
                    ? 1.0f - xrow[bb * XPAD + (int)((ff) & 2047u)]            \
                    :        xrow[bb * XPAD + (int)((ff) & 2047u)])           \
                : val[(int)((ff) & 0xFFFu) * VPAD + bb])
            const float v0 = FETCH(f0 & 0x8FFFu);
            const float v1 = FETCH(f1);
            const float v2 = FETCH(f2);
            const float v3 = FETCH(f3);
            #undef FETCH
            const float r = op ? (v0 + v1) + (v2 + v3)
                               : (v0 * v1) * (v2 * v3);
            val[(int)scid[j] * VPAD + bb] = r;
        }
        __syncthreads();
    }

    if (tid < BBK) out[blk * BBK + tid] = val[tid];   // root cid = 0
}

// ---------------------------------------------------------------------------
// Launch: x (f32), child_idx (i32), op_type (i32). One kernel; capturable.
// ---------------------------------------------------------------------------
extern "C" void kernel_launch(void* const* d_in, const int* in_sizes, int n_in,
                              void* d_out, int out_size) {
    const float* x         = (const float*)d_in[0];
    const int*   child_idx = (const int*)  d_in[1];
    const int*   op_type   = (const int*)  d_in[2];
    float*       out       = (float*)d_out;

    cudaFuncSetAttribute(eval_all,
                         cudaFuncAttributeMaxDynamicSharedMemorySize, SM_TOTAL);
    eval_all<<<NBLK, NTHR, SM_TOTAL>>>(x, child_idx, op_type, out);
}

// round 15
// speedup vs baseline: 29.7448x; 1.0682x over previous
#include <cuda_runtime.h>

#define B        1024
#define NUM_VARS 2048
#define LEAVES   4096
#define LEVELS   12
#define WIDTH    4096
#define NINT     (LEVELS * WIDTH)          // 49152
#define TOTAL    (LEAVES + NINT)           // 53248

#define NTHR     512
#define BBK      8                  // batch columns per block
#define NBLK     (B / BBK)          // 128 blocks
#define NDISC    384                // discovery threads (warps 0-11)

#define PCAP     1536               // max plan nodes on the fast path
#define HSZ      4096               // hash slots (power of two)
#define PROBE_MAX 256               // hash probe cap -> sFail (no hangs)
#define VPAD     9                  // val stride (9 coprime 32 -> conflict-free)
#define XPAD     2052               // floats; 8208 B row stride (16B aligned)

// Dense-fallback value buffer (touched only if plan exceeds PCAP / hash fills).
__device__ float g_dense[(size_t)NINT * B];

// ---- smem layout (bytes), 16B alignment where needed ----
#define SM_PCH   0                               // int4[PCAP]   raw children  24576
#define SM_SCH   (SM_PCH + PCAP * 16)            // int4[PCAP]   packed plan   24576
#define SM_XROW  (SM_SCH + PCAP * 16)            // float[8*XPAD]              65664
#define SM_VAL   (SM_XROW + BBK * XPAD * 4)      // float[PCAP*VPAD]           55296
#define SM_HKEY  (SM_VAL + PCAP * VPAD * 4)      // int[HSZ]                   16384
#define SM_PORIG (SM_HKEY + HSZ * 4)             // int[PCAP]                   6144
#define SM_META  (SM_PORIG + PCAP * 4)           // int[PCAP] level<<16|rank    6144
#define SM_HVAL  (SM_META + PCAP * 4)            // ushort[HSZ]                 8192
#define SM_POP   (SM_HVAL + HSZ * 2)             // uchar[PCAP]                 1536
#define SM_TOTAL (SM_POP + PCAP)                 // 208,512 B

#define BAR1() asm volatile("bar.sync 1, %0;" :: "n"(NDISC) : "memory")

__global__ void __launch_bounds__(NTHR, 1)
eval_all(const float* __restrict__ x,
         const int*   __restrict__ child_idx,
         const int*   __restrict__ op_type,
         float*       __restrict__ out)
{
    extern __shared__ unsigned char sm[];
    int4*           pch   = (int4*)          (sm + SM_PCH);
    int4*           sch   = (int4*)          (sm + SM_SCH);
    float*          xrow  = (float*)         (sm + SM_XROW);
    float*          val   = (float*)         (sm + SM_VAL);
    int*            hkey  = (int*)           (sm + SM_HKEY);
    int*            porig = (int*)           (sm + SM_PORIG);
    int*            meta  = (int*)           (sm + SM_META);
    unsigned short* hval  = (unsigned short*)(sm + SM_HVAL);
    unsigned char*  pop   = (unsigned char*) (sm + SM_POP);

    __shared__ int scnt, sFail, sNPh;
    __shared__ int slcnt[LEVELS], soff[LEVELS + 1];
    __shared__ int sMaxDep[LEVELS];              // max internal-child level per level
    __shared__ int sP[LEVELS + 1];               // phase boundaries (entry idx)

    const int tid = threadIdx.x;
    const int blk = blockIdx.x;

    if (tid < NDISC) {
        // =============== warps 0-11: worklist-BFS discovery ===============
        {   // vectorized hash init
            const int4 m1 = make_int4(-1, -1, -1, -1);
            for (int i = tid; i < HSZ / 4; i += NDISC) ((int4*)hkey)[i] = m1;
        }
        BAR1();
        if (tid == 0) {
            for (int l = 0; l < LEVELS; ++l) { slcnt[l] = 0; sMaxDep[l] = -1; }
            scnt = 1; sFail = 0;
            porig[0] = TOTAL - 1;                  // root = plan idx (cid) 0
            meta[0]  = (11 << 16) | 0;
            slcnt[11] = 1;
        }
        BAR1();

        int s = 0, e = 1;
        while (s < e) {
            for (int i = s + tid; i < e; i += NDISC) {
                const int ni = porig[i] - LEAVES;
                const int myLev = ni >> 12;                   // / WIDTH
                const int4 ch = ((const int4*)child_idx)[ni];
                pch[i] = ch;
                pop[i] = (unsigned char)op_type[ni];
                const int cs[4] = {ch.x, ch.y, ch.z, ch.w};
                int mdep = -1;
                #pragma unroll
                for (int f = 0; f < 4; ++f) {
                    const int c = cs[f];
                    if (c < LEAVES) continue;
                    const int ci = c - LEAVES;
                    const int l2 = ci >> 12;
                    if (l2 > mdep) mdep = l2;
                    // hash claim: single CAS probe chain (dedupe + insert)
                    unsigned slot = ((unsigned)c * 2654435761u) & (HSZ - 1);
                    int probes = 0;
                    while (true) {
                        const int old = atomicCAS(&hkey[slot], -1, c);
                        if (old == -1) {                      // we claimed c
                            const int cid = atomicAdd(&scnt, 1);
                            if (cid >= PCAP) { sFail = 1; break; }
                            porig[cid] = c;
                            const int r2 = atomicAdd(&slcnt[l2], 1);
                            meta[cid] = (l2 << 16) | r2;
                            hval[slot] = (unsigned short)cid;
                            break;
                        }
                        if (old == c) break;                  // duplicate
                        slot = (slot + 1) & (HSZ - 1);
                        if (++probes >= PROBE_MAX) { sFail = 1; break; }
                    }
                }
                if (mdep >= 0) atomicMax(&sMaxDep[myLev], mdep);
            }
            BAR1();   // wave's claims complete; scnt/sMaxDep stable
            s = e;
            const int sc = *(volatile int*)&scnt;
            e = (sc < PCAP) ? sc : PCAP;
            if (*(volatile int*)&sFail) break;
        }

        // ---- discovery tail: prefix offsets + dependency-merged phases ----
        if (tid == 0) {
            int o = 0;
            for (int l = 0; l < LEVELS; ++l) { soff[l] = o; o += slcnt[l]; }
            soff[LEVELS] = o;
            // greedy level->phase merge: level l joins phase starting at a
            // iff all its internal deps are below a (maxdep[l] < a).
            int nph = 0, a = 0;
            sP[0] = 0;
            for (int l = 1; l < LEVELS; ++l) {
                if (sMaxDep[l] >= a) { sP[++nph] = soff[l]; a = l; }
            }
            sP[++nph] = soff[LEVELS];
            sNPh = nph;
        }
    } else {
        // =============== warps 12-15: stage x rows into smem ===============
        for (int idx = tid - NDISC; idx < (BBK * NUM_VARS) / 4; idx += NTHR - NDISC) {
            const int r  = idx >> 9;                  // /512 float4 per row
            const int c4 = idx & 511;
            const float4 v =
                ((const float4*)x)[(size_t)(blk * BBK + r) * (NUM_VARS / 4) + c4];
            *(float4*)&xrow[r * XPAD + c4 * 4] = v;
        }
    }
    __syncthreads();   // join: plan metadata + xrow ready

    const int n = (*(volatile int*)&scnt < PCAP) ? scnt : PCAP;

    if (*(volatile int*)&sFail) {
        // =============== dense fallback (worst case only) ===============
        for (int l = 0; l < LEVELS; ++l) {
            for (int k = tid; k < WIDTH * BBK; k += NTHR) {
                const int w2 = k >> 3, b2 = k & 7, bg2 = blk * BBK + b2;
                const int ni = l * WIDTH + w2;
                const int4 ch = ((const int4*)child_idx)[ni];
                const int cs[4] = {ch.x, ch.y, ch.z, ch.w};
                float v[4];
                #pragma unroll
                for (int f = 0; f < 4; ++f) {
                    const int c = cs[f];
                    if (c < LEAVES) {
                        const float xv = xrow[b2 * XPAD + (c & (NUM_VARS - 1))];
                        v[f] = (c < NUM_VARS) ? xv : 1.0f - xv;
                    } else {
                        v[f] = g_dense[(size_t)(c - LEAVES) * B + bg2];
                    }
                }
                const float r = op_type[ni] ? (v[0] + v[1]) + (v[2] + v[3])
                                            : (v[0] * v[1]) * (v[2] * v[3]);
                g_dense[(size_t)ni * B + bg2] = r;
            }
            __syncthreads();
        }
        if (tid < BBK)
            out[blk * BBK + tid] = g_dense[(size_t)(NINT - 1) * B + blk * BBK + tid];
        return;
    }

    // ---- resolution: encode + scatter into level-sorted packed plan ----
    // 16-bit operand: bit15=leaf, bits0-11=leaf id or cid; op in bit14 of f0.
    // Packed entry: {f0|f1<<16, f2|f3<<16, dest cid, 0}.
    for (int i = tid; i < n; i += NTHR) {
        const int4 ch = pch[i];
        const int mt = meta[i];
        const int j  = soff[mt >> 16] + (mt & 0xFFFF);
        unsigned f[4];
        const int cs[4] = {ch.x, ch.y, ch.z, ch.w};
        #pragma unroll
        for (int q = 0; q < 4; ++q) {
            const int c = cs[q];
            if (c < LEAVES) f[q] = 0x8000u | (unsigned)c;
            else {
                unsigned slot = ((unsigned)c * 2654435761u) & (HSZ - 1);
                while (hkey[slot] != c) slot = (slot + 1) & (HSZ - 1);
                f[q] = hval[slot];
            }
        }
        f[0] |= ((unsigned)pop[i] & 1u) << 14;
        sch[j] = make_int4((int)(f[0] | (f[1] << 16)),
                           (int)(f[2] | (f[3] << 16)), i, 0);
    }
    __syncthreads();                              // plan finalized

    // ====== forward: merged dependency phases, 64 lanes x 8 columns ======
    const int lane = tid >> 3;                    // 0..63
    const int bb   = tid & 7;
    const int nph  = sNPh;

    for (int p = 0; p < nph; ++p) {
        const int s0 = sP[p], e0 = sP[p + 1];
        for (int j = s0 + lane; j < e0; j += 64) {
            const int4 e = sch[j];
            const unsigned f0 = (unsigned)e.x & 0xFFFFu;
            const unsigned f1 = (unsigned)e.x >> 16;
            const unsigned f2 = (unsigned)e.y & 0xFFFFu;
            const unsigned f3 = (unsigned)e.y >> 16;
            const int op = (f0 >> 14) & 1;
            #define FETCH(ff) (((ff) & 0x8000u)                               \
                ? (((ff) & 2048u)                                             \
                    ? 1.0f - xrow[bb * XPAD + (int)((ff) & 2047u)]            \
                    :        xrow[bb * XPAD + (int)((ff) & 2047u)])           \
                : val[(int)((ff) & 0xFFFu) * VPAD + bb])
            const float v0 = FETCH(f0 & 0x8FFFu);
            const float v1 = FETCH(f1);
            const float v2 = FETCH(f2);
            const float v3 = FETCH(f3);
            #undef FETCH
            const float r = op ? (v0 + v1) + (v2 + v3)
                               : (v0 * v1) * (v2 * v3);
            val[e.z * VPAD + bb] = r;
        }
        __syncthreads();
    }

    if (tid < BBK) out[blk * BBK + tid] = val[tid];   // root cid = 0
}

// ---------------------------------------------------------------------------
// Launch: x (f32), child_idx (i32), op_type (i32). One kernel; capturable.
// ---------------------------------------------------------------------------
extern "C" void kernel_launch(void* const* d_in, const int* in_sizes, int n_in,
                              void* d_out, int out_size) {
    const float* x         = (const float*)d_in[0];
    const int*   child_idx = (const int*)  d_in[1];
    const int*   op_type   = (const int*)  d_in[2];
    float*       out       = (float*)d_out;

    cudaFuncSetAttribute(eval_all,
                         cudaFuncAttributeMaxDynamicSharedMemorySize, SM_TOTAL);
    eval_all<<<NBLK, NTHR, SM_TOTAL>>>(x, child_idx, op_type, out);
}